// round 8
// baseline (speedup 1.0000x reference)
#include <cuda_runtime.h>
#include <stdint.h>

// out[i, 0:8] = params[idx[i]] * xs[i, 0:8]
// xs: float32 [N, 8]; idx: int32 [N]; params: float32 [V]; out: float32 [N, 8]
// N = 4194304, V = 1048576.
//
// TMA bulk pipeline v2: 3 input stages + 2 DECOUPLED output stages.
// Input refill never waits on store drain; store drain (wait_group.read 1)
// only gates reuse of an out-buffer two tiles later. All streaming traffic
// rides cp.async.bulk; the only LDG is the random param gather (L2-resident).

#define N_ROWS         4194304
#define TILE_ROWS      256
#define TILE_X4        (TILE_ROWS * 2)        // 512 float4 per tile
#define TILE_XS_BYTES  (TILE_X4 * 16)         // 8192
#define TILE_IDX_BYTES (TILE_ROWS * 4)        // 1024
#define IN_STAGES      3
#define OUT_STAGES     2
#define THREADS        256
#define ITEMS_PER_THR  (TILE_X4 / THREADS)    // 2
#define NUM_TILES      (N_ROWS / TILE_ROWS)   // 16384
#define TILES_PER_CTA  8
#define BLOCKS         (NUM_TILES / TILES_PER_CTA)  // 2048

__device__ __forceinline__ uint32_t smem_u32(const void* p) {
    return (uint32_t)__cvta_generic_to_shared(p);
}
__device__ __forceinline__ void mbar_init(uint32_t mbar, uint32_t count) {
    asm volatile("mbarrier.init.shared.b64 [%0], %1;" :: "r"(mbar), "r"(count) : "memory");
}
__device__ __forceinline__ void mbar_expect_tx(uint32_t mbar, uint32_t bytes) {
    asm volatile("mbarrier.arrive.expect_tx.shared.b64 _, [%0], %1;"
                 :: "r"(mbar), "r"(bytes) : "memory");
}
__device__ __forceinline__ void mbar_wait(uint32_t mbar, uint32_t parity) {
    asm volatile(
        "{\n\t"
        ".reg .pred P;\n\t"
        "WAIT_%=:\n\t"
        "mbarrier.try_wait.parity.shared.b64 P, [%0], %1, 0x989680;\n\t"
        "@P bra.uni DONE_%=;\n\t"
        "bra.uni WAIT_%=;\n\t"
        "DONE_%=:\n\t"
        "}"
        :: "r"(mbar), "r"(parity) : "memory");
}
__device__ __forceinline__ void bulk_load(uint32_t dst_smem, const void* src,
                                          uint32_t bytes, uint32_t mbar) {
    asm volatile(
        "cp.async.bulk.shared::cluster.global.mbarrier::complete_tx::bytes "
        "[%0], [%1], %2, [%3];"
        :: "r"(dst_smem), "l"(src), "r"(bytes), "r"(mbar) : "memory");
}
__device__ __forceinline__ void bulk_store(void* dst, uint32_t src_smem, uint32_t bytes) {
    asm volatile(
        "cp.async.bulk.global.shared::cta.bulk_group [%0], [%1], %2;"
        :: "l"(dst), "r"(src_smem), "r"(bytes) : "memory");
}

__global__ __launch_bounds__(THREADS) void gather_mul_tma_kernel(
    const float4* __restrict__ xs,     // [2N] float4
    const int*    __restrict__ idx,    // [N]
    const float*  __restrict__ params, // [V]
    float4*       __restrict__ out)    // [2N] float4
{
    __shared__ float4   s_xs [IN_STAGES][TILE_X4];    // 24 KB
    __shared__ int      s_idx[IN_STAGES][TILE_ROWS];  // 3 KB
    __shared__ float4   s_out[OUT_STAGES][TILE_X4];   // 16 KB
    __shared__ uint64_t s_mbar[IN_STAGES];

    const int tid = threadIdx.x;
    const bool leader = (tid == 0);
    const int tile0 = blockIdx.x * TILES_PER_CTA;

    uint32_t mbar_a[IN_STAGES];
#pragma unroll
    for (int s = 0; s < IN_STAGES; s++) mbar_a[s] = smem_u32(&s_mbar[s]);

    if (leader) {
#pragma unroll
        for (int s = 0; s < IN_STAGES; s++) mbar_init(mbar_a[s], 1);
    }
    __syncthreads();

    // Prologue: prefetch first IN_STAGES tiles.
    if (leader) {
#pragma unroll
        for (int s = 0; s < IN_STAGES; s++) {
            const int t = tile0 + s;
            mbar_expect_tx(mbar_a[s], TILE_XS_BYTES + TILE_IDX_BYTES);
            bulk_load(smem_u32(&s_xs[s][0]),  xs  + (size_t)t * TILE_X4,
                      TILE_XS_BYTES, mbar_a[s]);
            bulk_load(smem_u32(&s_idx[s][0]), idx + (size_t)t * TILE_ROWS,
                      TILE_IDX_BYTES, mbar_a[s]);
        }
    }

    int ph[IN_STAGES];
#pragma unroll
    for (int s = 0; s < IN_STAGES; s++) ph[s] = 0;

    for (int i = 0; i < TILES_PER_CTA; i++) {
        const int st = i % IN_STAGES;
        const int ob = i & 1;
        const int tile = tile0 + i;

        // Out-buffer ob was last stored at tile i-2: allow 1 outstanding
        // group (tile i-1's store) but require i-2's store to have read out.
        if (leader && i >= OUT_STAGES)
            asm volatile("cp.async.bulk.wait_group.read 1;" ::: "memory");

        mbar_wait(mbar_a[st], ph[st]);
        ph[st] ^= 1;
        __syncthreads();   // joins leader's wait_group with all threads

        // Compute: item m = tid + k*THREADS; row = m >> 1 (lane pairs share
        // the idx/param access -> broadcast).
        int j[ITEMS_PER_THR];
#pragma unroll
        for (int k = 0; k < ITEMS_PER_THR; k++)
            j[k] = s_idx[st][(tid + k * THREADS) >> 1];

        float p[ITEMS_PER_THR];
#pragma unroll
        for (int k = 0; k < ITEMS_PER_THR; k++)
            p[k] = __ldcg(params + j[k]);

#pragma unroll
        for (int k = 0; k < ITEMS_PER_THR; k++) {
            const int m = tid + k * THREADS;
            float4 v = s_xs[st][m];
            v.x *= p[k]; v.y *= p[k]; v.z *= p[k]; v.w *= p[k];
            s_out[ob][m] = v;
        }
        __syncthreads();   // compute done: s_out[ob] full, s_in[st] free

        if (leader) {
            asm volatile("fence.proxy.async;" ::: "memory");
            bulk_store(out + (size_t)tile * TILE_X4, smem_u32(&s_out[ob][0]),
                       TILE_XS_BYTES);
            asm volatile("cp.async.bulk.commit_group;" ::: "memory");

            const int ni = i + IN_STAGES;
            if (ni < TILES_PER_CTA) {   // refill: no store-drain dependency
                const int t = tile0 + ni;
                mbar_expect_tx(mbar_a[st], TILE_XS_BYTES + TILE_IDX_BYTES);
                bulk_load(smem_u32(&s_xs[st][0]),  xs  + (size_t)t * TILE_X4,
                          TILE_XS_BYTES, mbar_a[st]);
                bulk_load(smem_u32(&s_idx[st][0]), idx + (size_t)t * TILE_ROWS,
                          TILE_IDX_BYTES, mbar_a[st]);
            }
        }
    }

    // Drain all outstanding bulk stores before exit.
    if (leader)
        asm volatile("cp.async.bulk.wait_group 0;" ::: "memory");
}

extern "C" void kernel_launch(void* const* d_in, const int* in_sizes, int n_in,
                              void* d_out, int out_size)
{
    const float4* xs     = (const float4*)d_in[0];
    const int*    idx    = (const int*)d_in[1];
    const float*  params = (const float*)d_in[2];
    float4*       out    = (float4*)d_out;

    gather_mul_tma_kernel<<<BLOCKS, THREADS>>>(xs, idx, params, out);
}

// round 9
// speedup vs baseline: 1.6286x; 1.6286x over previous
#include <cuda_runtime.h>
#include <stdint.h>

// out[i, 0:8] = params[idx[i]] * xs[i, 0:8]
// xs: float32 [N, 8]; idx: int32 [N]; params: float32 [V]; out: float32 [N, 8]
// N = 4194304, V = 1048576.
//
// Best-measured structure (R4 + R5 gather): direct LDG/STG, 2 threads per
// row so every streaming access is a dense 16B lane-contiguous wavefront;
// lane pairs broadcast the idx/param access. Streams are evict-first
// (__ldcs/__stcs) so the 4 MB param table stays L2-resident; the gather is
// L2-only (__ldcg) since its lines have no L1 reuse. TMA/smem staging was
// tried (R7/R8) and regressed: zero-reuse streams are faster on the LDG path.

#define N_ROWS  4194304
#define ITEMS   (2 * N_ROWS)                   // 8M float4 half-rows
#define UNROLL  4
#define THREADS 256
#define BLOCKS  (ITEMS / (UNROLL * THREADS))   // 8192

__global__ __launch_bounds__(THREADS) void gather_mul_kernel(
    const float4* __restrict__ xs,     // [ITEMS]
    const int*    __restrict__ idx,    // [N] int32
    const float*  __restrict__ params, // [V]
    float4*       __restrict__ out)    // [ITEMS]
{
    const int t = blockIdx.x * THREADS + threadIdx.x;
    const int S = BLOCKS * THREADS;    // 2M items per sweep

    // 1) Batch index loads (lane pairs share an address -> broadcast).
    int j[UNROLL];
#pragma unroll
    for (int k = 0; k < UNROLL; k++)
        j[k] = __ldcs(idx + ((t + k * S) >> 1));

    // 2) Batch param gathers: L2-only, table is L2-resident.
    float p[UNROLL];
#pragma unroll
    for (int k = 0; k < UNROLL; k++)
        p[k] = __ldcg(params + j[k]);

    // 3) Batch xs half-row loads: 16B lane-contiguous, evict-first.
    float4 x[UNROLL];
#pragma unroll
    for (int k = 0; k < UNROLL; k++)
        x[k] = __ldcs(xs + t + k * S);

    // 4) Multiply + streaming stores (evict-first).
#pragma unroll
    for (int k = 0; k < UNROLL; k++) {
        float4 o;
        o.x = p[k] * x[k].x;
        o.y = p[k] * x[k].y;
        o.z = p[k] * x[k].z;
        o.w = p[k] * x[k].w;
        __stcs(out + t + k * S, o);
    }
}

extern "C" void kernel_launch(void* const* d_in, const int* in_sizes, int n_in,
                              void* d_out, int out_size)
{
    const float4* xs     = (const float4*)d_in[0];
    const int*    idx    = (const int*)d_in[1];
    const float*  params = (const float*)d_in[2];
    float4*       out    = (float4*)d_out;

    gather_mul_kernel<<<BLOCKS, THREADS>>>(xs, idx, params, out);
}